// round 4
// baseline (speedup 1.0000x reference)
#include <cuda_runtime.h>
#include <cuda_bf16.h>
#include <cstdint>

// Problem constants
#define BATCH 2
#define MQ    4096      // queries per batch
#define CCH   256       // channels (K)
#define HW    64        // image side, level 0
#define NPIX  (HW*HW)   // 4096

// Scratch: correlation pyramid (device globals = allowed scratch)
__device__ float g_corr0[BATCH * MQ * 64 * 64];  // 134.2 MB
__device__ float g_corr1[BATCH * MQ * 32 * 32];  //  33.5 MB
__device__ float g_corr2[BATCH * MQ * 16 * 16];  //   8.4 MB
__device__ float g_corr3[BATCH * MQ *  8 *  8];  //   2.1 MB

// ---------------------------------------------------------------------------
// TF32 helpers
// ---------------------------------------------------------------------------
__device__ __forceinline__ uint32_t f2tf32(float x) {
    uint32_t r;
    asm("cvt.rna.tf32.f32 %0, %1;" : "=r"(r) : "f"(x));
    return r;
}

__device__ __forceinline__ void mma_tf32(float* d, const uint32_t* a, const uint32_t* b) {
    asm volatile(
        "mma.sync.aligned.m16n8k8.row.col.f32.tf32.tf32.f32 "
        "{%0,%1,%2,%3}, {%4,%5,%6,%7}, {%8,%9}, {%0,%1,%2,%3};\n"
        : "+f"(d[0]), "+f"(d[1]), "+f"(d[2]), "+f"(d[3])
        : "r"(a[0]), "r"(a[1]), "r"(a[2]), "r"(a[3]),
          "r"(b[0]), "r"(b[1]));
}

// ---------------------------------------------------------------------------
// Kernel 1: corr[b] (4096x4096) = fmap1[b] (4096x256) @ fmap2[b] (256x4096)
// CTA tile 128x128, K-chunk 32, 8 warps each 64x32 (4x4 m16n8 tiles).
// ---------------------------------------------------------------------------
#define TK 32

__global__ __launch_bounds__(256, 2)
void gemm_kernel(const float* __restrict__ A, const float* __restrict__ Bm) {
    const int b     = blockIdx.z;
    const int mBase = blockIdx.y * 128;
    const int nBase = blockIdx.x * 128;
    const float* Ab = A  + (size_t)b * MQ  * CCH;   // row-major (M, K)
    const float* Bb = Bm + (size_t)b * CCH * NPIX;  // row-major (K, N)

    __shared__ uint32_t As[128][TK + 4];   // [m][k], pad 4 -> conflict-free frags
    __shared__ uint32_t Bs[TK][128 + 8];   // [k][n], pad 8 -> conflict-free frags

    const int tid    = threadIdx.x;
    const int warpId = tid >> 5;
    const int lane   = tid & 31;
    const int g      = lane >> 2;   // 0..7
    const int tg     = lane & 3;    // 0..3
    const int mWarp  = (warpId >> 2) * 64;  // 2 warp-rows
    const int nWarp  = (warpId & 3) * 32;   // 4 warp-cols

    float acc[4][4][4];
#pragma unroll
    for (int mt = 0; mt < 4; mt++)
#pragma unroll
        for (int nt = 0; nt < 4; nt++)
#pragma unroll
            for (int r = 0; r < 4; r++) acc[mt][nt][r] = 0.0f;

    for (int kk = 0; kk < CCH; kk += TK) {
        // Load A tile 128x32 (1024 float4, 4 per thread)
#pragma unroll
        for (int i = 0; i < 4; i++) {
            int f   = tid + 256 * i;
            int row = f >> 3;
            int c4  = (f & 7) << 2;
            float4 v = *(const float4*)(Ab + (size_t)(mBase + row) * CCH + kk + c4);
            uint4 t = make_uint4(f2tf32(v.x), f2tf32(v.y), f2tf32(v.z), f2tf32(v.w));
            *(uint4*)&As[row][c4] = t;
        }
        // Load B tile 32x128
#pragma unroll
        for (int i = 0; i < 4; i++) {
            int f   = tid + 256 * i;
            int row = f >> 5;
            int c4  = (f & 31) << 2;
            float4 v = *(const float4*)(Bb + (size_t)(kk + row) * NPIX + nBase + c4);
            uint4 t = make_uint4(f2tf32(v.x), f2tf32(v.y), f2tf32(v.z), f2tf32(v.w));
            *(uint4*)&Bs[row][c4] = t;
        }
        __syncthreads();

#pragma unroll
        for (int ks = 0; ks < TK; ks += 8) {
            uint32_t af[4][4], bf[4][2];
#pragma unroll
            for (int mt = 0; mt < 4; mt++) {
                int r = mWarp + mt * 16 + g;
                af[mt][0] = As[r][ks + tg];
                af[mt][1] = As[r + 8][ks + tg];
                af[mt][2] = As[r][ks + tg + 4];
                af[mt][3] = As[r + 8][ks + tg + 4];
            }
#pragma unroll
            for (int nt = 0; nt < 4; nt++) {
                int cn = nWarp + nt * 8 + g;
                bf[nt][0] = Bs[ks + tg][cn];
                bf[nt][1] = Bs[ks + tg + 4][cn];
            }
#pragma unroll
            for (int mt = 0; mt < 4; mt++)
#pragma unroll
                for (int nt = 0; nt < 4; nt++)
                    mma_tf32(acc[mt][nt], af[mt], bf[nt]);
        }
        __syncthreads();
    }

    // Epilogue -> g_corr0[(b*MQ + m) * NPIX + p]
    float* Cb = g_corr0 + (size_t)b * MQ * NPIX;
#pragma unroll
    for (int mt = 0; mt < 4; mt++) {
#pragma unroll
        for (int nt = 0; nt < 4; nt++) {
            int r0 = mBase + mWarp + mt * 16 + g;
            int c0 = nBase + nWarp + nt * 8 + 2 * tg;
            *(float2*)&Cb[(size_t)r0 * NPIX + c0] =
                make_float2(acc[mt][nt][0], acc[mt][nt][1]);
            *(float2*)&Cb[(size_t)(r0 + 8) * NPIX + c0] =
                make_float2(acc[mt][nt][2], acc[mt][nt][3]);
        }
    }
}

// ---------------------------------------------------------------------------
// Kernel 2: 2x2 average pool, level lvl -> lvl+1
// ---------------------------------------------------------------------------
__global__ void pool_kernel(int lvl) {
    const float* src = (lvl == 0) ? g_corr0 : (lvl == 1) ? g_corr1 : g_corr2;
    float*       dst = (lvl == 0) ? g_corr1 : (lvl == 1) ? g_corr2 : g_corr3;
    const int Wd = 32 >> lvl;            // dst side
    const int Ws = Wd * 2;               // src side
    const int total = BATCH * MQ * Wd * Wd;

    int i = blockIdx.x * blockDim.x + threadIdx.x;
    if (i >= total) return;
    int x   = i % Wd;
    int r   = i / Wd;
    int y   = r % Wd;
    int img = r / Wd;

    const float* s = src + ((size_t)img * Ws + 2 * y) * Ws + 2 * x;
    float2 a = *(const float2*)(s);
    float2 c = *(const float2*)(s + Ws);
    dst[i] = 0.25f * (a.x + a.y + c.x + c.y);
}

// ---------------------------------------------------------------------------
// Kernel 3: gather 10x10 windows per (query, level), blend bilinearly into
// the 9x9 outputs. 16 queries per block, 256 threads.
// out[b][lvl*81 + i*9 + j][m], i = x-offset index, j = y-offset index.
// ---------------------------------------------------------------------------
#define SQ 16

__global__ void sample_kernel(const float* __restrict__ cen, float* __restrict__ out) {
    __shared__ float Qs[4 * SQ * 101];   // stride 101 -> bank-conflict-free
    __shared__ float fxs[4 * SQ];
    __shared__ float fys[4 * SQ];
    __shared__ float cxy[SQ * 2];

    const int tid = threadIdx.x;
    const int q0  = blockIdx.x * SQ;

    if (tid < SQ * 2) cxy[tid] = cen[q0 * 2 + tid];
    __syncthreads();

    // Phase 1: load 4*SQ*100 taps (zero OOB)
    for (int u = tid; u < 4 * SQ * 100; u += 256) {
        int lvl = u / (SQ * 100);
        int rem = u - lvl * (SQ * 100);
        int qi  = rem / 100;
        int tp  = rem - qi * 100;
        int a   = tp % 10;   // x-offset idx (consecutive u -> consecutive X)
        int bb  = tp / 10;   // y-offset idx

        float sc  = 1.0f / (float)(1 << lvl);
        float cx  = cxy[qi * 2 + 0] * sc;
        float cy  = cxy[qi * 2 + 1] * sc;
        float flx = floorf(cx), fly = floorf(cy);
        int X = (int)flx - 4 + a;
        int Y = (int)fly - 4 + bb;
        int Wl = 64 >> lvl;

        const float* vp = (lvl == 0) ? g_corr0 : (lvl == 1) ? g_corr1
                         : (lvl == 2) ? g_corr2 : g_corr3;
        float v = 0.0f;
        if (X >= 0 && X < Wl && Y >= 0 && Y < Wl)
            v = vp[((size_t)(q0 + qi) * Wl + Y) * Wl + X];
        Qs[(lvl * SQ + qi) * 101 + a * 10 + bb] = v;
        if (tp == 0) {
            fxs[lvl * SQ + qi] = cx - flx;
            fys[lvl * SQ + qi] = cy - fly;
        }
    }
    __syncthreads();

    // Phase 2: 324 channels x SQ queries, coalesced writes over m
    for (int f = tid; f < 324 * SQ; f += 256) {
        int qi = f & (SQ - 1);
        int ch = f >> 4;
        int lvl = ch / 81;
        int o   = ch - lvl * 81;
        int i   = o / 9;
        int j   = o - i * 9;

        float fx = fxs[lvl * SQ + qi];
        float fy = fys[lvl * SQ + qi];
        const float* Qb = Qs + (lvl * SQ + qi) * 101;
        float q00 = Qb[i * 10 + j];
        float q10 = Qb[(i + 1) * 10 + j];
        float q01 = Qb[i * 10 + j + 1];
        float q11 = Qb[(i + 1) * 10 + j + 1];
        float val = (1.0f - fy) * ((1.0f - fx) * q00 + fx * q10)
                  +         fy  * ((1.0f - fx) * q01 + fx * q11);

        int q = q0 + qi;
        int b = q >> 12;        // / 4096
        int m = q & 4095;
        out[((size_t)b * 324 + ch) * (size_t)MQ + m] = val;
    }
}

// ---------------------------------------------------------------------------
// Launch
// ---------------------------------------------------------------------------
extern "C" void kernel_launch(void* const* d_in, const int* in_sizes, int n_in,
                              void* d_out, int out_size) {
    const float* fmap1 = (const float*)d_in[0];  // (B, M, C)
    const float* fmap2 = (const float*)d_in[1];  // (B, C, H, W)
    const float* cen   = (const float*)d_in[2];  // (B, M, 2)
    float* out         = (float*)d_out;          // (B, 324, M)

    dim3 ggrid(NPIX / 128, MQ / 128, BATCH);     // 32 x 32 x 2
    gemm_kernel<<<ggrid, 256>>>(fmap1, fmap2);

    pool_kernel<<<(BATCH * MQ * 32 * 32 + 255) / 256, 256>>>(0);
    pool_kernel<<<(BATCH * MQ * 16 * 16 + 255) / 256, 256>>>(1);
    pool_kernel<<<(BATCH * MQ *  8 *  8 + 255) / 256, 256>>>(2);

    sample_kernel<<<(BATCH * MQ) / SQ, 256>>>(cen, out);
}

// round 9
// speedup vs baseline: 1.1820x; 1.1820x over previous
#include <cuda_runtime.h>
#include <cuda_bf16.h>
#include <cstdint>

// Problem constants
#define BATCH 2
#define MQ    4096
#define CCH   256
#define NPIX  4096

// -------- scratch (device globals = allowed scratch) --------
__device__ float g_a[BATCH * MQ * CCH];        // tf32-rounded fmap1 (8 MB)
__device__ float g_b[BATCH * CCH * NPIX];      // tf32-rounded fmap2 (8 MB)
__device__ float g_corr0[BATCH * MQ * 4096];   // 134 MB level-0 volume
__device__ float g_corr1[BATCH * MQ * 1024];   //  33 MB (from GEMM epilogue)
__device__ float g_corr2[BATCH * MQ * 256];
__device__ float g_corr3[BATCH * MQ * 64];

// -------- helpers --------
__device__ __forceinline__ uint32_t smem_u32(const void* p) {
    uint32_t a;
    asm("{ .reg .u64 t; cvta.to.shared.u64 t, %1; cvt.u32.u64 %0, t; }"
        : "=r"(a) : "l"(p));
    return a;
}
__device__ __forceinline__ uint32_t f2tf32(float x) {
    uint32_t r;
    asm("cvt.rna.tf32.f32 %0, %1;" : "=r"(r) : "f"(x));
    return r;
}
__device__ __forceinline__ void cp16(uint32_t dst, const void* src) {
    asm volatile("cp.async.cg.shared.global [%0], [%1], 16;\n"
                 :: "r"(dst), "l"(src));
}
#define CP_COMMIT() asm volatile("cp.async.commit_group;\n" ::: "memory")
#define CP_WAIT1()  asm volatile("cp.async.wait_group 1;\n" ::: "memory")
#define CP_WAIT0()  asm volatile("cp.async.wait_group 0;\n" ::: "memory")

__device__ __forceinline__ void mma_tf32(float* d, const uint32_t* a, const uint32_t* b) {
    asm volatile(
        "mma.sync.aligned.m16n8k8.row.col.f32.tf32.tf32.f32 "
        "{%0,%1,%2,%3}, {%4,%5,%6,%7}, {%8,%9}, {%0,%1,%2,%3};\n"
        : "+f"(d[0]), "+f"(d[1]), "+f"(d[2]), "+f"(d[3])
        : "r"(a[0]), "r"(a[1]), "r"(a[2]), "r"(a[3]),
          "r"(b[0]), "r"(b[1]));
}

// ---------------------------------------------------------------------------
// Kernel 0: round both inputs to tf32 precision (stored as f32), so the GEMM
// can cp.async raw bytes with numerics identical to cvt-at-stage-time.
// ---------------------------------------------------------------------------
__global__ void round_kernel(const float* __restrict__ f1, const float* __restrict__ f2) {
    const size_t NA = (size_t)BATCH * MQ * CCH;   // 2M
    size_t i = ((size_t)blockIdx.x * 256 + threadIdx.x) * 4;
    if (i < NA) {
        float4 v = *(const float4*)(f1 + i);
        float4 t = make_float4(__uint_as_float(f2tf32(v.x)), __uint_as_float(f2tf32(v.y)),
                               __uint_as_float(f2tf32(v.z)), __uint_as_float(f2tf32(v.w)));
        *(float4*)(g_a + i) = t;
    } else {
        size_t j = i - NA;
        float4 v = *(const float4*)(f2 + j);
        float4 t = make_float4(__uint_as_float(f2tf32(v.x)), __uint_as_float(f2tf32(v.y)),
                               __uint_as_float(f2tf32(v.z)), __uint_as_float(f2tf32(v.w)));
        *(float4*)(g_b + j) = t;
    }
}

// ---------------------------------------------------------------------------
// Kernel 1: corr0[b] (4096x4096) = A[b] (4096x256) @ B[b] (256x4096)
// CTA tile 128x128, K-chunks of 32, 3-stage cp.async pipeline.
// 8 warps, each a 64x32 warp tile (4x4 m16n8k8).
// Epilogue also emits the level-1 2x2-pooled tile (a 128-col N-tile spans
// exactly 2 image rows, so the pool quads are CTA-local).
// ---------------------------------------------------------------------------
#define A_ROWPAD 36     // floats per A row (32 + 4); 144 B, 16B-aligned
#define B_ROWPAD 136    // floats per B row (128 + 8); 544 B, 16B-aligned
#define A_BYTES  (128 * A_ROWPAD * 4)     // 18432
#define B_BYTES  (32 * B_ROWPAD * 4)      // 17408
#define STAGE_B  (A_BYTES + B_BYTES)      // 35840
#define SMEM_T   (3 * STAGE_B)            // 107520

__global__ void __launch_bounds__(256, 2)
corr_gemm() {
    extern __shared__ char smem[];
    const uint32_t sb = smem_u32(smem);
    const int tid = threadIdx.x;
    const int warpId = tid >> 5, lane = tid & 31;
    const int g  = lane >> 2;                // 0..7
    const int tg = lane & 3;                 // 0..3
    const int mWarp = (warpId >> 2) * 64;
    const int nWarp = (warpId & 3) * 32;

    const int b     = blockIdx.z;
    const int mBase = blockIdx.y * 128;
    const int nBase = blockIdx.x * 128;
    const float* Ap = g_a + (size_t)b * MQ * CCH + (size_t)mBase * CCH;
    const float* Bp = g_b + (size_t)b * CCH * NPIX;

    float acc[4][4][4];
#pragma unroll
    for (int mt = 0; mt < 4; mt++)
#pragma unroll
        for (int nt = 0; nt < 4; nt++)
#pragma unroll
            for (int r = 0; r < 4; r++) acc[mt][nt][r] = 0.0f;

    // ---- stage issue ----
    auto stage_chunk = [&](int st, int ch) {
        const int k0 = ch * 32;
        const uint32_t abase = sb + st * STAGE_B;
        const uint32_t bbase = abase + A_BYTES;
#pragma unroll
        for (int it = 0; it < 4; it++) {
            int f = tid + 256 * it;
            int row = f >> 3, seg = f & 7;
            cp16(abase + row * (A_ROWPAD * 4) + seg * 16,
                 Ap + (size_t)row * CCH + k0 + seg * 4);
        }
#pragma unroll
        for (int it = 0; it < 4; it++) {
            int f = tid + 256 * it;
            int r = f >> 5, seg = f & 31;
            cp16(bbase + r * (B_ROWPAD * 4) + seg * 16,
                 Bp + (size_t)(k0 + r) * NPIX + nBase + seg * 4);
        }
    };

    stage_chunk(0, 0); CP_COMMIT();
    stage_chunk(1, 1); CP_COMMIT();

    for (int ch = 0; ch < 8; ch++) {
        if (ch < 7) CP_WAIT1(); else CP_WAIT0();
        __syncthreads();
        if (ch + 2 < 8) { stage_chunk((ch + 2) % 3, ch + 2); CP_COMMIT(); }

        const int st = ch % 3;
        const uint32_t (*As)[A_ROWPAD] =
            (const uint32_t(*)[A_ROWPAD])(smem + st * STAGE_B);
        const uint32_t (*Bs)[B_ROWPAD] =
            (const uint32_t(*)[B_ROWPAD])(smem + st * STAGE_B + A_BYTES);

#pragma unroll
        for (int ks = 0; ks < 32; ks += 8) {
            uint32_t af[4][4], bf[4][2];
#pragma unroll
            for (int mt = 0; mt < 4; mt++) {
                int r = mWarp + mt * 16 + g;
                af[mt][0] = As[r][ks + tg];
                af[mt][1] = As[r + 8][ks + tg];
                af[mt][2] = As[r][ks + tg + 4];
                af[mt][3] = As[r + 8][ks + tg + 4];
            }
#pragma unroll
            for (int nt = 0; nt < 4; nt++) {
                int cn = nWarp + nt * 8 + g;
                bf[nt][0] = Bs[ks + tg][cn];
                bf[nt][1] = Bs[ks + tg + 4][cn];
            }
#pragma unroll
            for (int mt = 0; mt < 4; mt++)
#pragma unroll
                for (int nt = 0; nt < 4; nt++)
                    mma_tf32(acc[mt][nt], af[mt], bf[nt]);
        }
    }
    __syncthreads();   // pipeline done; SMEM reusable for epilogue

    // ---- epilogue: write corr0 + stage tile for level-1 pool ----
    float (*Cs)[132] = (float(*)[132])smem;   // 128 x 132 floats = 67.6 KB
    float* Cb = g_corr0 + ((size_t)(b * MQ + mBase)) * NPIX;
#pragma unroll
    for (int mt = 0; mt < 4; mt++) {
#pragma unroll
        for (int nt = 0; nt < 4; nt++) {
            int r0 = mWarp + mt * 16 + g;
            int c0 = nWarp + nt * 8 + 2 * tg;
            float d0 = acc[mt][nt][0], d1 = acc[mt][nt][1];
            float d2 = acc[mt][nt][2], d3 = acc[mt][nt][3];
            *(float2*)&Cb[(size_t)r0 * NPIX + nBase + c0] = make_float2(d0, d1);
            *(float2*)&Cb[(size_t)(r0 + 8) * NPIX + nBase + c0] = make_float2(d2, d3);
            Cs[r0][c0] = d0;     Cs[r0][c0 + 1] = d1;
            Cs[r0 + 8][c0] = d2; Cs[r0 + 8][c0 + 1] = d3;
        }
    }
    __syncthreads();

    // level-1 pool: this N-tile = image rows (nBase/64, nBase/64+1) -> l1 row nBase/128
    {
        const int mL = tid >> 1;
        const int hf = tid & 1;
        const int trow = nBase >> 7;
        float* C1 = g_corr1 + ((size_t)(b * MQ + mBase + mL)) * 1024 + trow * 32 + hf * 16;
#pragma unroll
        for (int j4 = 0; j4 < 16; j4 += 4) {
            float4 v;
            float* vo = &v.x;
#pragma unroll
            for (int e = 0; e < 4; e++) {
                int c = 2 * (hf * 16 + j4 + e);
                vo[e] = 0.25f * (Cs[mL][c] + Cs[mL][c + 1] +
                                 Cs[mL][c + 64] + Cs[mL][c + 65]);
            }
            *(float4*)(C1 + j4) = v;
        }
    }
}

// ---------------------------------------------------------------------------
// Kernel 2: pool corr1 -> corr2 -> corr3. One block per (b,m) image.
// ---------------------------------------------------------------------------
__global__ void pool23_kernel() {
    const int img = blockIdx.x;              // b*MQ + m, 8192 total
    const int tid = threadIdx.x;
    __shared__ float s1[1024];
    __shared__ float s2[256];

    *(float4*)&s1[tid * 4] = *(const float4*)(g_corr1 + (size_t)img * 1024 + tid * 4);
    __syncthreads();
    {
        int x = tid & 15, y = tid >> 4;
        const float* p = s1 + (2 * y) * 32 + 2 * x;
        float v = 0.25f * (p[0] + p[1] + p[32] + p[33]);
        g_corr2[(size_t)img * 256 + tid] = v;
        s2[tid] = v;
    }
    __syncthreads();
    if (tid < 64) {
        int x = tid & 7, y = tid >> 3;
        const float* p = s2 + (2 * y) * 16 + 2 * x;
        g_corr3[(size_t)img * 64 + tid] = 0.25f * (p[0] + p[1] + p[16] + p[17]);
    }
}

// ---------------------------------------------------------------------------
// Kernel 3: gather 10x10 integer windows per (query, level), bilinear blend.
// ---------------------------------------------------------------------------
#define SQ 16

__global__ void sample_kernel(const float* __restrict__ cen, float* __restrict__ out) {
    __shared__ float Qs[4 * SQ * 101];
    __shared__ float fxs[4 * SQ];
    __shared__ float fys[4 * SQ];
    __shared__ float cxy[SQ * 2];

    const int tid = threadIdx.x;
    const int q0  = blockIdx.x * SQ;

    if (tid < SQ * 2) cxy[tid] = cen[q0 * 2 + tid];
    __syncthreads();

    for (int u = tid; u < 4 * SQ * 100; u += 256) {
        int lvl = u / (SQ * 100);
        int rem = u - lvl * (SQ * 100);
        int qi  = rem / 100;
        int tp  = rem - qi * 100;
        int a   = tp % 10;
        int bb  = tp / 10;

        float sc  = 1.0f / (float)(1 << lvl);
        float cx  = cxy[qi * 2 + 0] * sc;
        float cy  = cxy[qi * 2 + 1] * sc;
        float flx = floorf(cx), fly = floorf(cy);
        int X = (int)flx - 4 + a;
        int Y = (int)fly - 4 + bb;
        int Wl = 64 >> lvl;

        const float* vp = (lvl == 0) ? g_corr0 : (lvl == 1) ? g_corr1
                         : (lvl == 2) ? g_corr2 : g_corr3;
        float v = 0.0f;
        if (X >= 0 && X < Wl && Y >= 0 && Y < Wl)
            v = vp[((size_t)(q0 + qi) * Wl + Y) * Wl + X];
        Qs[(lvl * SQ + qi) * 101 + a * 10 + bb] = v;
        if (tp == 0) {
            fxs[lvl * SQ + qi] = cx - flx;
            fys[lvl * SQ + qi] = cy - fly;
        }
    }
    __syncthreads();

    for (int f = tid; f < 324 * SQ; f += 256) {
        int qi = f & (SQ - 1);
        int ch = f >> 4;
        int lvl = ch / 81;
        int o   = ch - lvl * 81;
        int i   = o / 9;
        int j   = o - i * 9;

        float fx = fxs[lvl * SQ + qi];
        float fy = fys[lvl * SQ + qi];
        const float* Qb = Qs + (lvl * SQ + qi) * 101;
        float q00 = Qb[i * 10 + j];
        float q10 = Qb[(i + 1) * 10 + j];
        float q01 = Qb[i * 10 + j + 1];
        float q11 = Qb[(i + 1) * 10 + j + 1];
        float val = (1.0f - fy) * ((1.0f - fx) * q00 + fx * q10)
                  +         fy  * ((1.0f - fx) * q01 + fx * q11);

        int q = q0 + qi;
        int b = q >> 12;
        int m = q & 4095;
        out[((size_t)b * 324 + ch) * (size_t)MQ + m] = val;
    }
}

// ---------------------------------------------------------------------------
// Launch
// ---------------------------------------------------------------------------
extern "C" void kernel_launch(void* const* d_in, const int* in_sizes, int n_in,
                              void* d_out, int out_size) {
    const float* fmap1 = (const float*)d_in[0];  // (B, M, C)
    const float* fmap2 = (const float*)d_in[1];  // (B, C, H, W)
    const float* cen   = (const float*)d_in[2];  // (B, M, 2)
    float* out         = (float*)d_out;          // (B, 324, M)

    cudaFuncSetAttribute(corr_gemm, cudaFuncAttributeMaxDynamicSharedMemorySize, SMEM_T);

    round_kernel<<<4096, 256>>>(fmap1, fmap2);              // 4M float4-elems
    corr_gemm<<<dim3(32, 32, BATCH), 256, SMEM_T>>>();
    pool23_kernel<<<BATCH * MQ, 256>>>();
    sample_kernel<<<(BATCH * MQ) / SQ, 256>>>(cen, out);
}

// round 10
// speedup vs baseline: 1.3984x; 1.1831x over previous
#include <cuda_runtime.h>
#include <cuda_fp16.h>
#include <cstdint>

// Problem constants
#define BATCH 2
#define MQ    4096
#define CCH   256
#define NPIX  4096

// -------- scratch (device globals = allowed scratch) --------
__device__ __half g_a[BATCH * MQ * CCH];       // fp16 fmap1 (4 MB)
__device__ __half g_bT[BATCH * NPIX * CCH];    // fp16 fmap2 transposed (pixel, ch) (4 MB)
__device__ float g_corr0[BATCH * MQ * 4096];   // 134 MB level-0 volume
__device__ float g_corr1[BATCH * MQ * 1024];   //  33 MB (from GEMM epilogue)
__device__ float g_corr2[BATCH * MQ * 256];
__device__ float g_corr3[BATCH * MQ * 64];

// -------- helpers --------
__device__ __forceinline__ uint32_t smem_u32(const void* p) {
    uint32_t a;
    asm("{ .reg .u64 t; cvta.to.shared.u64 t, %1; cvt.u32.u64 %0, t; }"
        : "=r"(a) : "l"(p));
    return a;
}
__device__ __forceinline__ void cp16(uint32_t dst, const void* src) {
    asm volatile("cp.async.cg.shared.global [%0], [%1], 16;\n"
                 :: "r"(dst), "l"(src));
}
#define CP_COMMIT() asm volatile("cp.async.commit_group;\n" ::: "memory")
#define CP_WAIT1()  asm volatile("cp.async.wait_group 1;\n" ::: "memory")
#define CP_WAIT0()  asm volatile("cp.async.wait_group 0;\n" ::: "memory")

__device__ __forceinline__ void mma_f16(float* d, const uint32_t* a, const uint32_t* b) {
    asm volatile(
        "mma.sync.aligned.m16n8k16.row.col.f32.f16.f16.f32 "
        "{%0,%1,%2,%3}, {%4,%5,%6,%7}, {%8,%9}, {%0,%1,%2,%3};\n"
        : "+f"(d[0]), "+f"(d[1]), "+f"(d[2]), "+f"(d[3])
        : "r"(a[0]), "r"(a[1]), "r"(a[2]), "r"(a[3]),
          "r"(b[0]), "r"(b[1]));
}

// ---------------------------------------------------------------------------
// Kernel 0a: fmap1 -> fp16 g_a (elementwise)
// ---------------------------------------------------------------------------
__global__ void convA_kernel(const float* __restrict__ f1) {
    size_t i = ((size_t)blockIdx.x * 256 + threadIdx.x) * 4;
    float4 v = *(const float4*)(f1 + i);
    __half2 lo = __floats2half2_rn(v.x, v.y);
    __half2 hi = __floats2half2_rn(v.z, v.w);
    *(uint2*)&g_a[i] = make_uint2(*(uint32_t*)&lo, *(uint32_t*)&hi);
}

// ---------------------------------------------------------------------------
// Kernel 0b: fmap2 (B, C, NPIX) -> g_bT (B, NPIX, C) fp16, 32x32 SMEM tiles
// ---------------------------------------------------------------------------
__global__ void transB_kernel(const float* __restrict__ f2) {
    __shared__ float tile[32][33];
    const int b  = blockIdx.z;
    const int x0 = blockIdx.x * 32;   // pixel
    const int c0 = blockIdx.y * 32;   // channel
    const int tx = threadIdx.x, ty = threadIdx.y;   // 32 x 8
    const float* src = f2 + (size_t)b * CCH * NPIX;
#pragma unroll
    for (int i = 0; i < 4; i++)
        tile[ty + 8 * i][tx] = src[(size_t)(c0 + ty + 8 * i) * NPIX + x0 + tx];
    __syncthreads();
    __half* dst = g_bT + (size_t)b * NPIX * CCH;
#pragma unroll
    for (int i = 0; i < 4; i++)
        dst[(size_t)(x0 + ty + 8 * i) * CCH + c0 + tx] =
            __float2half_rn(tile[tx][ty + 8 * i]);
}

// ---------------------------------------------------------------------------
// Kernel 1: corr0[b] = A[b] (4096x256) @ B[b]^T, fp16 mma m16n8k16.
// CTA tile 128x128, K-chunks of 64, 3-stage cp.async pipeline.
// 8 warps, each 64x32 warp tile (4x4 m16n8). Epilogue fuses level-1 pool.
// ---------------------------------------------------------------------------
#define KC 64
#define A_ROWU 36     // uint32 per A row: 32 (64 halves) + 4 pad -> 144 B
#define B_ROWU 36
#define A_BYTES  (128 * A_ROWU * 4)      // 18432
#define B_BYTES  (128 * B_ROWU * 4)      // 18432
#define STAGE_B  (A_BYTES + B_BYTES)     // 36864
#define SMEM_T   (3 * STAGE_B)           // 110592

__global__ void __launch_bounds__(256, 1)
corr_gemm() {
    extern __shared__ char smem[];
    const uint32_t sb = smem_u32(smem);
    const int tid = threadIdx.x;
    const int warpId = tid >> 5, lane = tid & 31;
    const int g  = lane >> 2;                // 0..7
    const int tg = lane & 3;                 // 0..3
    const int mWarp = (warpId >> 2) * 64;
    const int nWarp = (warpId & 3) * 32;

    const int b     = blockIdx.z;
    const int mBase = blockIdx.y * 128;
    const int nBase = blockIdx.x * 128;
    const __half* Ap = g_a  + (size_t)b * MQ * CCH + (size_t)mBase * CCH;
    const __half* Bp = g_bT + (size_t)b * NPIX * CCH + (size_t)nBase * CCH;

    float acc[4][4][4];
#pragma unroll
    for (int mt = 0; mt < 4; mt++)
#pragma unroll
        for (int nt = 0; nt < 4; nt++)
#pragma unroll
            for (int r = 0; r < 4; r++) acc[mt][nt][r] = 0.0f;

    // ---- stage one K-chunk (A rows + B rows, both k-contiguous fp16) ----
    auto stage_chunk = [&](int st, int ch) {
        const int k0 = ch * KC;
        const uint32_t abase = sb + st * STAGE_B;
        const uint32_t bbase = abase + A_BYTES;
#pragma unroll
        for (int it = 0; it < 4; it++) {
            int f = tid + 256 * it;
            int row = f >> 3, seg = f & 7;        // seg: 8 halves = 16B
            cp16(abase + row * (A_ROWU * 4) + seg * 16,
                 Ap + (size_t)row * CCH + k0 + seg * 8);
        }
#pragma unroll
        for (int it = 0; it < 4; it++) {
            int f = tid + 256 * it;
            int row = f >> 3, seg = f & 7;
            cp16(bbase + row * (B_ROWU * 4) + seg * 16,
                 Bp + (size_t)row * CCH + k0 + seg * 8);
        }
    };

    stage_chunk(0, 0); CP_COMMIT();
    stage_chunk(1, 1); CP_COMMIT();

    for (int ch = 0; ch < 4; ch++) {
        if (ch < 3) CP_WAIT1(); else CP_WAIT0();
        __syncthreads();
        if (ch + 2 < 4) { stage_chunk((ch + 2) % 3, ch + 2); CP_COMMIT(); }

        const int st = ch % 3;
        const uint32_t (*As)[A_ROWU] =
            (const uint32_t(*)[A_ROWU])(smem + st * STAGE_B);
        const uint32_t (*Bs)[B_ROWU] =
            (const uint32_t(*)[B_ROWU])(smem + st * STAGE_B + A_BYTES);

#pragma unroll
        for (int ks = 0; ks < KC / 2; ks += 8) {      // uint32 offset per k16 step
            uint32_t af[4][4], bf[4][2];
#pragma unroll
            for (int mt = 0; mt < 4; mt++) {
                int r = mWarp + mt * 16 + g;
                af[mt][0] = As[r][ks + tg];           // row g,   k 2tg..2tg+1
                af[mt][1] = As[r + 8][ks + tg];       // row g+8
                af[mt][2] = As[r][ks + tg + 4];       // row g,   k 2tg+8..
                af[mt][3] = As[r + 8][ks + tg + 4];
            }
#pragma unroll
            for (int nt = 0; nt < 4; nt++) {
                int cn = nWarp + nt * 8 + g;
                bf[nt][0] = Bs[cn][ks + tg];          // col g, k 2tg..2tg+1
                bf[nt][1] = Bs[cn][ks + tg + 4];      // col g, k 2tg+8..
            }
#pragma unroll
            for (int mt = 0; mt < 4; mt++)
#pragma unroll
                for (int nt = 0; nt < 4; nt++)
                    mma_f16(acc[mt][nt], af[mt], bf[nt]);
        }
    }
    __syncthreads();   // pipeline done; SMEM reusable for epilogue

    // ---- epilogue: write corr0 + stage tile for fused level-1 pool ----
    float (*Cs)[132] = (float(*)[132])smem;
    float* Cb = g_corr0 + ((size_t)(b * MQ + mBase)) * NPIX;
#pragma unroll
    for (int mt = 0; mt < 4; mt++) {
#pragma unroll
        for (int nt = 0; nt < 4; nt++) {
            int r0 = mWarp + mt * 16 + g;
            int c0 = nWarp + nt * 8 + 2 * tg;
            float d0 = acc[mt][nt][0], d1 = acc[mt][nt][1];
            float d2 = acc[mt][nt][2], d3 = acc[mt][nt][3];
            *(float2*)&Cb[(size_t)r0 * NPIX + nBase + c0] = make_float2(d0, d1);
            *(float2*)&Cb[(size_t)(r0 + 8) * NPIX + nBase + c0] = make_float2(d2, d3);
            Cs[r0][c0] = d0;     Cs[r0][c0 + 1] = d1;
            Cs[r0 + 8][c0] = d2; Cs[r0 + 8][c0 + 1] = d3;
        }
    }
    __syncthreads();

    // level-1 pool: N-tile = image rows (nBase/64, nBase/64+1) -> l1 row nBase/128
    {
        const int mL = tid >> 1;
        const int hf = tid & 1;
        const int trow = nBase >> 7;
        float* C1 = g_corr1 + ((size_t)(b * MQ + mBase + mL)) * 1024 + trow * 32 + hf * 16;
#pragma unroll
        for (int j4 = 0; j4 < 16; j4 += 4) {
            float4 v;
            float* vo = &v.x;
#pragma unroll
            for (int e = 0; e < 4; e++) {
                int c = 2 * (hf * 16 + j4 + e);
                vo[e] = 0.25f * (Cs[mL][c] + Cs[mL][c + 1] +
                                 Cs[mL][c + 64] + Cs[mL][c + 65]);
            }
            *(float4*)(C1 + j4) = v;
        }
    }
}

// ---------------------------------------------------------------------------
// Kernel 2: pool corr1 -> corr2 -> corr3. One block per (b,m) image.
// ---------------------------------------------------------------------------
__global__ void pool23_kernel() {
    const int img = blockIdx.x;              // b*MQ + m, 8192 total
    const int tid = threadIdx.x;
    __shared__ float s1[1024];
    __shared__ float s2[256];

    *(float4*)&s1[tid * 4] = *(const float4*)(g_corr1 + (size_t)img * 1024 + tid * 4);
    __syncthreads();
    {
        int x = tid & 15, y = tid >> 4;
        const float* p = s1 + (2 * y) * 32 + 2 * x;
        float v = 0.25f * (p[0] + p[1] + p[32] + p[33]);
        g_corr2[(size_t)img * 256 + tid] = v;
        s2[tid] = v;
    }
    __syncthreads();
    if (tid < 64) {
        int x = tid & 7, y = tid >> 3;
        const float* p = s2 + (2 * y) * 16 + 2 * x;
        g_corr3[(size_t)img * 64 + tid] = 0.25f * (p[0] + p[1] + p[16] + p[17]);
    }
}

// ---------------------------------------------------------------------------
// Kernel 3: gather 10x10 integer windows per (query, level), bilinear blend.
// SQ=8 -> 1024 blocks for occupancy.
// ---------------------------------------------------------------------------
#define SQ 8

__global__ void sample_kernel(const float* __restrict__ cen, float* __restrict__ out) {
    __shared__ float Qs[4 * SQ * 101];
    __shared__ float fxs[4 * SQ];
    __shared__ float fys[4 * SQ];
    __shared__ float cxy[SQ * 2];

    const int tid = threadIdx.x;
    const int q0  = blockIdx.x * SQ;

    if (tid < SQ * 2) cxy[tid] = cen[q0 * 2 + tid];
    __syncthreads();

    for (int u = tid; u < 4 * SQ * 100; u += 256) {
        int lvl = u / (SQ * 100);
        int rem = u - lvl * (SQ * 100);
        int qi  = rem / 100;
        int tp  = rem - qi * 100;
        int a   = tp % 10;
        int bb  = tp / 10;

        float sc  = 1.0f / (float)(1 << lvl);
        float cx  = cxy[qi * 2 + 0] * sc;
        float cy  = cxy[qi * 2 + 1] * sc;
        float flx = floorf(cx), fly = floorf(cy);
        int X = (int)flx - 4 + a;
        int Y = (int)fly - 4 + bb;
        int Wl = 64 >> lvl;

        const float* vp = (lvl == 0) ? g_corr0 : (lvl == 1) ? g_corr1
                         : (lvl == 2) ? g_corr2 : g_corr3;
        float v = 0.0f;
        if (X >= 0 && X < Wl && Y >= 0 && Y < Wl)
            v = vp[((size_t)(q0 + qi) * Wl + Y) * Wl + X];
        Qs[(lvl * SQ + qi) * 101 + a * 10 + bb] = v;
        if (tp == 0) {
            fxs[lvl * SQ + qi] = cx - flx;
            fys[lvl * SQ + qi] = cy - fly;
        }
    }
    __syncthreads();

    for (int f = tid; f < 324 * SQ; f += 256) {
        int qi = f & (SQ - 1);
        int ch = f / SQ;
        int lvl = ch / 81;
        int o   = ch - lvl * 81;
        int i   = o / 9;
        int j   = o - i * 9;

        float fx = fxs[lvl * SQ + qi];
        float fy = fys[lvl * SQ + qi];
        const float* Qb = Qs + (lvl * SQ + qi) * 101;
        float q00 = Qb[i * 10 + j];
        float q10 = Qb[(i + 1) * 10 + j];
        float q01 = Qb[i * 10 + j + 1];
        float q11 = Qb[(i + 1) * 10 + j + 1];
        float val = (1.0f - fy) * ((1.0f - fx) * q00 + fx * q10)
                  +         fy  * ((1.0f - fx) * q01 + fx * q11);

        int q = q0 + qi;
        int b = q >> 12;
        int m = q & 4095;
        out[((size_t)b * 324 + ch) * (size_t)MQ + m] = val;
    }
}

// ---------------------------------------------------------------------------
// Launch
// ---------------------------------------------------------------------------
extern "C" void kernel_launch(void* const* d_in, const int* in_sizes, int n_in,
                              void* d_out, int out_size) {
    const float* fmap1 = (const float*)d_in[0];  // (B, M, C)
    const float* fmap2 = (const float*)d_in[1];  // (B, C, H, W)
    const float* cen   = (const float*)d_in[2];  // (B, M, 2)
    float* out         = (float*)d_out;          // (B, 324, M)

    cudaFuncSetAttribute(corr_gemm, cudaFuncAttributeMaxDynamicSharedMemorySize, SMEM_T);

    convA_kernel<<<(BATCH * MQ * CCH / 4) / 256, 256>>>(fmap1);
    transB_kernel<<<dim3(NPIX / 32, CCH / 32, BATCH), dim3(32, 8)>>>(fmap2);
    corr_gemm<<<dim3(32, 32, BATCH), 256, SMEM_T>>>();
    pool23_kernel<<<BATCH * MQ, 256>>>();
    sample_kernel<<<(BATCH * MQ) / SQ, 256>>>(cen, out);
}

// round 11
// speedup vs baseline: 1.5319x; 1.0955x over previous
#include <cuda_runtime.h>
#include <cuda_fp16.h>
#include <cstdint>

// Problem constants
#define BATCH 2
#define MQ    4096
#define CCH   256
#define NPIX  4096

// -------- scratch (device globals = allowed scratch) --------
__device__ __half g_a[BATCH * MQ * CCH];       // fp16 fmap1 (4 MB)
__device__ __half g_bT[BATCH * NPIX * CCH];    // fp16 fmap2 transposed (pixel, ch) (4 MB)
__device__ float g_corr0[BATCH * MQ * 4096];   // 134 MB level-0 volume
__device__ float g_corr1[BATCH * MQ * 1024];   //  33 MB (from GEMM epilogue)
__device__ float g_corr2[BATCH * MQ * 256];
__device__ float g_corr3[BATCH * MQ * 64];

// -------- helpers --------
__device__ __forceinline__ uint32_t smem_u32(const void* p) {
    uint32_t a;
    asm("{ .reg .u64 t; cvta.to.shared.u64 t, %1; cvt.u32.u64 %0, t; }"
        : "=r"(a) : "l"(p));
    return a;
}
__device__ __forceinline__ void cp16(uint32_t dst, const void* src) {
    asm volatile("cp.async.cg.shared.global [%0], [%1], 16;\n"
                 :: "r"(dst), "l"(src));
}
#define CP_COMMIT() asm volatile("cp.async.commit_group;\n" ::: "memory")
#define CP_WAIT1()  asm volatile("cp.async.wait_group 1;\n" ::: "memory")
#define CP_WAIT0()  asm volatile("cp.async.wait_group 0;\n" ::: "memory")

__device__ __forceinline__ void ldsm_x4(uint32_t* r, uint32_t addr) {
    asm volatile("ldmatrix.sync.aligned.m8n8.x4.shared.b16 {%0,%1,%2,%3}, [%4];"
        : "=r"(r[0]), "=r"(r[1]), "=r"(r[2]), "=r"(r[3]) : "r"(addr));
}
__device__ __forceinline__ void mma_f16(float* d, const uint32_t* a, const uint32_t* b) {
    asm volatile(
        "mma.sync.aligned.m16n8k16.row.col.f32.f16.f16.f32 "
        "{%0,%1,%2,%3}, {%4,%5,%6,%7}, {%8,%9}, {%0,%1,%2,%3};\n"
        : "+f"(d[0]), "+f"(d[1]), "+f"(d[2]), "+f"(d[3])
        : "r"(a[0]), "r"(a[1]), "r"(a[2]), "r"(a[3]),
          "r"(b[0]), "r"(b[1]));
}

// ---------------------------------------------------------------------------
// Kernel 0a: fmap1 -> fp16 g_a (elementwise)
// ---------------------------------------------------------------------------
__global__ void convA_kernel(const float* __restrict__ f1) {
    size_t i = ((size_t)blockIdx.x * 256 + threadIdx.x) * 4;
    float4 v = *(const float4*)(f1 + i);
    __half2 lo = __floats2half2_rn(v.x, v.y);
    __half2 hi = __floats2half2_rn(v.z, v.w);
    *(uint2*)&g_a[i] = make_uint2(*(uint32_t*)&lo, *(uint32_t*)&hi);
}

// ---------------------------------------------------------------------------
// Kernel 0b: fmap2 (B, C, NPIX) -> g_bT (B, NPIX, C) fp16, 32x32 SMEM tiles
// ---------------------------------------------------------------------------
__global__ void transB_kernel(const float* __restrict__ f2) {
    __shared__ float tile[32][33];
    const int b  = blockIdx.z;
    const int x0 = blockIdx.x * 32;   // pixel
    const int c0 = blockIdx.y * 32;   // channel
    const int tx = threadIdx.x, ty = threadIdx.y;   // 32 x 8
    const float* src = f2 + (size_t)b * CCH * NPIX;
#pragma unroll
    for (int i = 0; i < 4; i++)
        tile[ty + 8 * i][tx] = src[(size_t)(c0 + ty + 8 * i) * NPIX + x0 + tx];
    __syncthreads();
    __half* dst = g_bT + (size_t)b * NPIX * CCH;
#pragma unroll
    for (int i = 0; i < 4; i++)
        dst[(size_t)(x0 + ty + 8 * i) * CCH + c0 + tx] =
            __float2half_rn(tile[tx][ty + 8 * i]);
}

// ---------------------------------------------------------------------------
// Kernel 1: corr0[b] = A[b] (4096x256) @ B[b]^T, fp16 mma m16n8k16 + ldmatrix.
// CTA tile 128x128, K-chunks of 64, 3-stage cp.async pipeline.
// 8 warps, each 64x32 warp tile (4x4 m16n8). Epilogue fuses level-1 pool.
// Row pitch 144B (9 x 16B, pitch == 1 mod 8 slots) -> all LDSM phases
// bank-conflict-free without XOR swizzle.
// ---------------------------------------------------------------------------
#define KC 64
#define ROWB 144                          // bytes per SMEM row (64 halves + pad)
#define A_BYTES  (128 * ROWB)             // 18432
#define B_BYTES  (128 * ROWB)             // 18432
#define STAGE_B  (A_BYTES + B_BYTES)      // 36864
#define SMEM_T   (3 * STAGE_B)            // 110592

__global__ void __launch_bounds__(256, 1)
corr_gemm() {
    extern __shared__ char smem[];
    const uint32_t sb = smem_u32(smem);
    const int tid = threadIdx.x;
    const int warpId = tid >> 5, lane = tid & 31;
    const int g  = lane >> 2;                // 0..7
    const int tg = lane & 3;                 // 0..3
    const int mWarp = (warpId >> 2) * 64;
    const int nWarp = (warpId & 3) * 32;

    const int b     = blockIdx.z;
    const int mBase = blockIdx.y * 128;
    const int nBase = blockIdx.x * 128;
    const __half* Ap = g_a  + (size_t)b * MQ * CCH + (size_t)mBase * CCH;
    const __half* Bp = g_bT + (size_t)b * NPIX * CCH + (size_t)nBase * CCH;

    // --- per-lane ldmatrix source offsets (stage-invariant) ---
    // A x4 for tile mt: submatrices (m0-7,kLo),(m8-15,kLo),(m0-7,kHi),(m8-15,kHi)
    //   lane groups 0-15 -> m rows 0-15, kLo; 16-31 -> m rows 0-15, kHi
    uint32_t aLane[4];
#pragma unroll
    for (int mt = 0; mt < 4; mt++)
        aLane[mt] = (uint32_t)((mWarp + mt * 16 + (lane & 15)) * ROWB
                               + ((lane >> 4) * 8) * 2);
    // B x4 for nt-pair np: regs = (n0-7,kLo),(n0-7,kHi),(n8-15,kLo),(n8-15,kHi)
    //   lanes 0-7: n+0..7 kLo; 8-15: n+0..7 kHi; 16-23: n+8..15 kLo; 24-31: kHi
    uint32_t bLane[2];
#pragma unroll
    for (int np = 0; np < 2; np++)
        bLane[np] = (uint32_t)(A_BYTES
                    + (nWarp + np * 16 + (lane & 7) + ((lane >> 4) & 1) * 8) * ROWB
                    + (((lane >> 3) & 1) * 8) * 2);

    float acc[4][4][4];
#pragma unroll
    for (int mt = 0; mt < 4; mt++)
#pragma unroll
        for (int nt = 0; nt < 4; nt++)
#pragma unroll
            for (int r = 0; r < 4; r++) acc[mt][nt][r] = 0.0f;

    // ---- stage one K-chunk (A rows + B rows, both k-contiguous fp16) ----
    auto stage_chunk = [&](int st, int ch) {
        const int k0 = ch * KC;
        const uint32_t abase = sb + st * STAGE_B;
        const uint32_t bbase = abase + A_BYTES;
#pragma unroll
        for (int it = 0; it < 4; it++) {
            int f = tid + 256 * it;
            int row = f >> 3, seg = f & 7;        // seg: 8 halves = 16B
            cp16(abase + row * ROWB + seg * 16,
                 Ap + (size_t)row * CCH + k0 + seg * 8);
        }
#pragma unroll
        for (int it = 0; it < 4; it++) {
            int f = tid + 256 * it;
            int row = f >> 3, seg = f & 7;
            cp16(bbase + row * ROWB + seg * 16,
                 Bp + (size_t)row * CCH + k0 + seg * 8);
        }
    };

    stage_chunk(0, 0); CP_COMMIT();
    stage_chunk(1, 1); CP_COMMIT();

    for (int ch = 0; ch < 4; ch++) {
        if (ch < 3) CP_WAIT1(); else CP_WAIT0();
        __syncthreads();
        if (ch + 2 < 4) { stage_chunk((ch + 2) % 3, ch + 2); CP_COMMIT(); }

        const uint32_t stbase = sb + (ch % 3) * STAGE_B;

#pragma unroll
        for (int kk = 0; kk < KC / 16; kk++) {     // 4 k16 steps
            uint32_t af[4][4], bf[2][4];
#pragma unroll
            for (int mt = 0; mt < 4; mt++)
                ldsm_x4(af[mt], stbase + aLane[mt] + kk * 32);
#pragma unroll
            for (int np = 0; np < 2; np++)
                ldsm_x4(bf[np], stbase + bLane[np] + kk * 32);
#pragma unroll
            for (int mt = 0; mt < 4; mt++)
#pragma unroll
                for (int np = 0; np < 2; np++) {
                    mma_f16(acc[mt][2 * np],     af[mt], &bf[np][0]);
                    mma_f16(acc[mt][2 * np + 1], af[mt], &bf[np][2]);
                }
        }
    }
    __syncthreads();   // pipeline done; SMEM reusable for epilogue

    // ---- epilogue: write corr0 + stage tile for fused level-1 pool ----
    float (*Cs)[132] = (float(*)[132])smem;
    float* Cb = g_corr0 + ((size_t)(b * MQ + mBase)) * NPIX;
#pragma unroll
    for (int mt = 0; mt < 4; mt++) {
#pragma unroll
        for (int nt = 0; nt < 4; nt++) {
            int r0 = mWarp + mt * 16 + g;
            int c0 = nWarp + nt * 8 + 2 * tg;
            float d0 = acc[mt][nt][0], d1 = acc[mt][nt][1];
            float d2 = acc[mt][nt][2], d3 = acc[mt][nt][3];
            *(float2*)&Cb[(size_t)r0 * NPIX + nBase + c0] = make_float2(d0, d1);
            *(float2*)&Cb[(size_t)(r0 + 8) * NPIX + nBase + c0] = make_float2(d2, d3);
            Cs[r0][c0] = d0;     Cs[r0][c0 + 1] = d1;
            Cs[r0 + 8][c0] = d2; Cs[r0 + 8][c0 + 1] = d3;
        }
    }
    __syncthreads();

    // level-1 pool: N-tile = image rows (nBase/64, nBase/64+1) -> l1 row nBase/128
    {
        const int mL = tid >> 1;
        const int hf = tid & 1;
        const int trow = nBase >> 7;
        float* C1 = g_corr1 + ((size_t)(b * MQ + mBase + mL)) * 1024 + trow * 32 + hf * 16;
#pragma unroll
        for (int j4 = 0; j4 < 16; j4 += 4) {
            float4 v;
            float* vo = &v.x;
#pragma unroll
            for (int e = 0; e < 4; e++) {
                int c = 2 * (hf * 16 + j4 + e);
                vo[e] = 0.25f * (Cs[mL][c] + Cs[mL][c + 1] +
                                 Cs[mL][c + 64] + Cs[mL][c + 65]);
            }
            *(float4*)(C1 + j4) = v;
        }
    }
}

// ---------------------------------------------------------------------------
// Kernel 2: pool corr1 -> corr2 -> corr3. One block per (b,m) image.
// ---------------------------------------------------------------------------
__global__ void pool23_kernel() {
    const int img = blockIdx.x;              // b*MQ + m, 8192 total
    const int tid = threadIdx.x;
    __shared__ float s1[1024];
    __shared__ float s2[256];

    *(float4*)&s1[tid * 4] = *(const float4*)(g_corr1 + (size_t)img * 1024 + tid * 4);
    __syncthreads();
    {
        int x = tid & 15, y = tid >> 4;
        const float* p = s1 + (2 * y) * 32 + 2 * x;
        float v = 0.25f * (p[0] + p[1] + p[32] + p[33]);
        g_corr2[(size_t)img * 256 + tid] = v;
        s2[tid] = v;
    }
    __syncthreads();
    if (tid < 64) {
        int x = tid & 7, y = tid >> 3;
        const float* p = s2 + (2 * y) * 16 + 2 * x;
        g_corr3[(size_t)img * 64 + tid] = 0.25f * (p[0] + p[1] + p[16] + p[17]);
    }
}

// ---------------------------------------------------------------------------
// Kernel 3: gather 10x10 integer windows per (query, level), bilinear blend.
// SQ=8 -> 1024 blocks for occupancy.
// ---------------------------------------------------------------------------
#define SQ 8

__global__ void sample_kernel(const float* __restrict__ cen, float* __restrict__ out) {
    __shared__ float Qs[4 * SQ * 101];
    __shared__ float fxs[4 * SQ];
    __shared__ float fys[4 * SQ];
    __shared__ float cxy[SQ * 2];

    const int tid = threadIdx.x;
    const int q0  = blockIdx.x * SQ;

    if (tid < SQ * 2) cxy[tid] = cen[q0 * 2 + tid];
    __syncthreads();

    for (int u = tid; u < 4 * SQ * 100; u += 256) {
        int lvl = u / (SQ * 100);
        int rem = u - lvl * (SQ * 100);
        int qi  = rem / 100;
        int tp  = rem - qi * 100;
        int a   = tp % 10;
        int bb  = tp / 10;

        float sc  = 1.0f / (float)(1 << lvl);
        float cx  = cxy[qi * 2 + 0] * sc;
        float cy  = cxy[qi * 2 + 1] * sc;
        float flx = floorf(cx), fly = floorf(cy);
        int X = (int)flx - 4 + a;
        int Y = (int)fly - 4 + bb;
        int Wl = 64 >> lvl;

        const float* vp = (lvl == 0) ? g_corr0 : (lvl == 1) ? g_corr1
                         : (lvl == 2) ? g_corr2 : g_corr3;
        float v = 0.0f;
        if (X >= 0 && X < Wl && Y >= 0 && Y < Wl)
            v = vp[((size_t)(q0 + qi) * Wl + Y) * Wl + X];
        Qs[(lvl * SQ + qi) * 101 + a * 10 + bb] = v;
        if (tp == 0) {
            fxs[lvl * SQ + qi] = cx - flx;
            fys[lvl * SQ + qi] = cy - fly;
        }
    }
    __syncthreads();

    for (int f = tid; f < 324 * SQ; f += 256) {
        int qi = f & (SQ - 1);
        int ch = f / SQ;
        int lvl = ch / 81;
        int o   = ch - lvl * 81;
        int i   = o / 9;
        int j   = o - i * 9;

        float fx = fxs[lvl * SQ + qi];
        float fy = fys[lvl * SQ + qi];
        const float* Qb = Qs + (lvl * SQ + qi) * 101;
        float q00 = Qb[i * 10 + j];
        float q10 = Qb[(i + 1) * 10 + j];
        float q01 = Qb[i * 10 + j + 1];
        float q11 = Qb[(i + 1) * 10 + j + 1];
        float val = (1.0f - fy) * ((1.0f - fx) * q00 + fx * q10)
                  +         fy  * ((1.0f - fx) * q01 + fx * q11);

        int q = q0 + qi;
        int b = q >> 12;
        int m = q & 4095;
        out[((size_t)b * 324 + ch) * (size_t)MQ + m] = val;
    }
}

// ---------------------------------------------------------------------------
// Launch
// ---------------------------------------------------------------------------
extern "C" void kernel_launch(void* const* d_in, const int* in_sizes, int n_in,
                              void* d_out, int out_size) {
    const float* fmap1 = (const float*)d_in[0];  // (B, M, C)
    const float* fmap2 = (const float*)d_in[1];  // (B, C, H, W)
    const float* cen   = (const float*)d_in[2];  // (B, M, 2)
    float* out         = (float*)d_out;          // (B, 324, M)

    cudaFuncSetAttribute(corr_gemm, cudaFuncAttributeMaxDynamicSharedMemorySize, SMEM_T);

    convA_kernel<<<(BATCH * MQ * CCH / 4) / 256, 256>>>(fmap1);
    transB_kernel<<<dim3(NPIX / 32, CCH / 32, BATCH), dim3(32, 8)>>>(fmap2);
    corr_gemm<<<dim3(32, 32, BATCH), 256, SMEM_T>>>();
    pool23_kernel<<<BATCH * MQ, 256>>>();
    sample_kernel<<<(BATCH * MQ) / SQ, 256>>>(cen, out);
}